// round 9
// baseline (speedup 1.0000x reference)
#include <cuda_runtime.h>
#include <cstdint>
#include <cstddef>

// FPS with EXACT spatial pruning: B=8, N=131072, NPOINT=1024.
// 8 clusters (batch each) x 8 CTAs x 512 threads.
// One-time: Morton(32^3) counting-sort of each batch's points into
// g_reorder (float4 xyz+origidx); groups = 64 consecutive points,
// round-robin across the batch's 8 CTAs; per-group bounding sphere.
// Steady state per step:
//   check: skip group iff (dist(gc,c)-r)^2 * 0.998 > cached groupmax  (exact)
//   work queue: warps pop active groups, update mindist (SMEM), REDUX
//               (max dist, min orig idx) -> group meta {v,i,x,y,z}
//   reduce: metas -> warpred -> DSMEM slots -> barrier.cluster ->
//           every warp reduces 8 slots -> next centroid in registers.
// Skipped groups keep cached meta => output bit-identical to brute force.

#define NB       8
#define NPTS     131072
#define NSAMP    1024
#define CSIZE    8
#define TPB      512
#define PPB      (NPTS / CSIZE)      // 16384 points per CTA
#define NWARPS   (TPB / 32)          // 16
#define NCELLS   32768               // 32^3 Morton cells
#define GRPSZ    64
#define NGRP_B   (NPTS / GRPSZ)      // 2048 groups per batch
#define NGRP_C   (NGRP_B / CSIZE)    // 256 groups per CTA

static __device__ float4   g_reorder[NB][NPTS];    // 16 MB scratch (L2-resident)
static __device__ unsigned g_hist[NB][NCELLS];     // 1 MB (re-zeroed every launch)

struct __align__(16) Red { unsigned v, i; float x, y, z; unsigned pad[3]; };  // 32B

struct Smem {
    float    mind[NGRP_C * GRPSZ];   // 64 KB  per-point mindist
    float4   gsph[NGRP_C];           // 4 KB   center.xyz, inflated radius
    Red      meta[NGRP_C];           // 8 KB   cached {maxdist, argidx, coords}
    Red      warpred[NWARPS];
    Red      slots[2][CSIZE];
    unsigned queue[NGRP_C];
    unsigned scanp[512];
    int      qcount, qtake;
};

// ---------- asm helpers ----------
__device__ __forceinline__ unsigned ctarank() {
    unsigned r; asm("mov.u32 %0, %%cluster_ctarank;" : "=r"(r)); return r;
}
__device__ __forceinline__ unsigned cvta_s(const void* p) {
    unsigned r;
    asm("{ .reg .u64 t; cvta.to.shared.u64 t, %1; cvt.u32.u64 %0, t; }"
        : "=r"(r) : "l"(p));
    return r;
}
__device__ __forceinline__ unsigned mapa_s(unsigned laddr, unsigned rank) {
    unsigned r;
    asm("mapa.shared::cluster.u32 %0, %1, %2;" : "=r"(r) : "r"(laddr), "r"(rank));
    return r;
}
__device__ __forceinline__ void st_cluster_v4(unsigned raddr, unsigned a, unsigned b,
                                              unsigned c, unsigned d) {
    asm volatile("st.shared::cluster.v4.b32 [%0], {%1,%2,%3,%4};"
                 :: "r"(raddr), "r"(a), "r"(b), "r"(c), "r"(d) : "memory");
}
__device__ __forceinline__ void st_cluster_u32(unsigned raddr, unsigned v) {
    asm volatile("st.shared::cluster.u32 [%0], %1;" :: "r"(raddr), "r"(v) : "memory");
}
__device__ __forceinline__ void cluster_bar() {
    asm volatile("barrier.cluster.arrive.aligned;" ::: "memory");
    asm volatile("barrier.cluster.wait.aligned;"   ::: "memory");
}
__device__ __forceinline__ unsigned p1b2(unsigned x) {   // interleave 10->30 bits
    x &= 0x3ffu;
    x = (x | (x << 16)) & 0x030000FFu;
    x = (x | (x << 8))  & 0x0300F00Fu;
    x = (x | (x << 4))  & 0x030C30C3u;
    x = (x | (x << 2))  & 0x09249249u;
    return x;
}
__device__ __forceinline__ unsigned cell_of(float x, float y, float z) {
    int cx = (int)((x + 5.0f) * 3.2f); cx = cx < 0 ? 0 : (cx > 31 ? 31 : cx);
    int cy = (int)((y + 5.0f) * 3.2f); cy = cy < 0 ? 0 : (cy > 31 ? 31 : cy);
    int cz = (int)((z + 5.0f) * 3.2f); cz = cz < 0 ? 0 : (cz > 31 ? 31 : cz);
    return p1b2((unsigned)cx) | (p1b2((unsigned)cy) << 1) | (p1b2((unsigned)cz) << 2);
}

__global__ void __launch_bounds__(TPB, 1)
fps_kernel(const float* __restrict__ xyz, float* __restrict__ out) {
    extern __shared__ __align__(16) unsigned char smem_raw[];
    Smem* s = reinterpret_cast<Smem*>(smem_raw);

    const int      tid  = threadIdx.x;
    const unsigned lane = tid & 31;
    const unsigned warp = (unsigned)tid >> 5;
    const unsigned rank = ctarank();
    const int      batch = blockIdx.x / CSIZE;

    const float* __restrict__ base = xyz + (size_t)batch * NPTS * 3;
    unsigned* __restrict__ hb = g_hist[batch];
    float4*   __restrict__ rb = g_reorder[batch];

    // ================= one-time spatial binning =================
    // P0: zero this batch's histogram
    for (int i = (int)rank * (NCELLS / CSIZE) + tid;
         i < (int)(rank + 1) * (NCELLS / CSIZE); i += TPB)
        hb[i] = 0u;
    cluster_bar();

    // P1: histogram of this CTA's 16384 points
    for (int ii = tid; ii < PPB; ii += TPB) {
        unsigned gi = rank * PPB + (unsigned)ii;
        const float* p = base + (size_t)gi * 3;
        float x = __ldg(p), y = __ldg(p + 1), z = __ldg(p + 2);
        atomicAdd(&hb[cell_of(x, y, z)], 1u);
    }
    cluster_bar();

    // P2: exclusive prefix scan of 32768 counts (rank-0 CTA only)
    if (rank == 0) {
        const int per = NCELLS / TPB;        // 64
        unsigned ssum = 0;
        for (int j = 0; j < per; ++j) ssum += hb[tid * per + j];
        s->scanp[tid] = ssum;
        __syncthreads();
        if (tid == 0) {
            unsigned run = 0;
            for (int i = 0; i < TPB; ++i) { unsigned v = s->scanp[i]; s->scanp[i] = run; run += v; }
        }
        __syncthreads();
        unsigned run = s->scanp[tid];
        for (int j = 0; j < per; ++j) {
            unsigned v = hb[tid * per + j];
            hb[tid * per + j] = run;
            run += v;
        }
    }
    cluster_bar();

    // P3: scatter points (xyz + original batch-local index) to Morton order
    for (int ii = tid; ii < PPB; ii += TPB) {
        unsigned gi = rank * PPB + (unsigned)ii;
        const float* p = base + (size_t)gi * 3;
        float x = __ldg(p), y = __ldg(p + 1), z = __ldg(p + 2);
        unsigned slot = atomicAdd(&hb[cell_of(x, y, z)], 1u);
        rb[slot] = make_float4(x, y, z, __uint_as_float(gi));
    }
    cluster_bar();

    // P4: build per-group bounding spheres + init mindist/meta
    for (int i = tid; i < NGRP_C * GRPSZ; i += TPB)
        s->mind[i] = __int_as_float(0x7f800000);
    for (int kk = 0; kk < NGRP_C / NWARPS; ++kk) {       // 16 groups per warp
        int k = (int)warp * (NGRP_C / NWARPS) + kk;
        const float4* rp = rb + ((unsigned)k * CSIZE + rank) * GRPSZ;
        float4 p0 = __ldg(rp + 2 * lane);
        float4 p1 = __ldg(rp + 2 * lane + 1);
        float sx = p0.x + p1.x, sy = p0.y + p1.y, sz = p0.z + p1.z;
#pragma unroll
        for (int off = 16; off > 0; off >>= 1) {
            sx += __shfl_xor_sync(0xffffffffu, sx, off);
            sy += __shfl_xor_sync(0xffffffffu, sy, off);
            sz += __shfl_xor_sync(0xffffffffu, sz, off);
        }
        float gx = sx * (1.0f / GRPSZ), gy = sy * (1.0f / GRPSZ), gz = sz * (1.0f / GRPSZ);
        float dx0 = p0.x - gx, dy0 = p0.y - gy, dz0 = p0.z - gz;
        float dx1 = p1.x - gx, dy1 = p1.y - gy, dz1 = p1.z - gz;
        float d2 = fmaxf(dx0 * dx0 + dy0 * dy0 + dz0 * dz0,
                         dx1 * dx1 + dy1 * dy1 + dz1 * dz1);
        unsigned md = __reduce_max_sync(0xffffffffu, __float_as_uint(d2));
        if (lane == 0) {
            float rad = sqrtf(__uint_as_float(md)) * 1.001f + 1e-6f;
            s->gsph[k] = make_float4(gx, gy, gz, rad);
            s->meta[k].v = 0x7f800000u;   // +inf: never skipped in step 1
            s->meta[k].i = 0u;
        }
    }

    // remote slot addresses (warp0 lanes < CSIZE), both parities
    unsigned rs0 = 0, rs1 = 0;
    if (warp == 0 && lane < CSIZE) {
        rs0 = mapa_s(cvta_s(&s->slots[0][rank]), lane);
        rs1 = mapa_s(cvta_s(&s->slots[1][rank]), lane);
    }

    // initial centroid = point 0 of this batch
    float cx = __ldg(base + 0);
    float cy = __ldg(base + 1);
    float cz = __ldg(base + 2);
    if (rank == 0 && tid == 0) {
        float* o = out + (size_t)batch * NSAMP * 3;
        o[0] = cx; o[1] = cy; o[2] = cz;
    }
    __syncthreads();
    cluster_bar();   // spheres/mindist ready everywhere before step 1

    // ================= steady-state FPS loop =================
    for (int t = 1; t < NSAMP; ++t) {
        if (tid == 0) { s->qcount = 0; s->qtake = 0; }
        __syncthreads();

        // ---- check phase: build active-group queue (threads 0..255) ----
        bool active = false;
        if (tid < NGRP_C) {
            float4 gs = s->gsph[tid];
            float gmax = __uint_as_float(s->meta[tid].v);
            float dx = gs.x - cx, dy = gs.y - cy, dz = gs.z - cz;
            float dc2 = dx * dx + dy * dy + dz * dz;
            float tt = sqrtf(dc2) - gs.w;
            bool skip = (tt > 0.0f) && (0.998f * tt * tt > gmax);
            active = !skip;
        }
        unsigned bal = __ballot_sync(0xffffffffu, active);
        if (bal) {
            int cnt = __popc(bal);
            unsigned pos = 0;
            if (lane == 0) pos = (unsigned)atomicAdd(&s->qcount, cnt);
            pos = __shfl_sync(0xffffffffu, pos, 0);
            if (active)
                s->queue[pos + __popc(bal & ((1u << lane) - 1u))] = (unsigned)tid;
        }
        __syncthreads();
        const int nq = s->qcount;

        // ---- work loop: warps pop active groups ----
        for (;;) {
            int g = 0;
            if (lane == 0) g = atomicAdd(&s->qtake, 1);
            g = __shfl_sync(0xffffffffu, g, 0);
            if (g >= nq) break;
            const int k = (int)s->queue[g];

            const float4* rp = rb + ((unsigned)k * CSIZE + rank) * GRPSZ;
            float4 p0 = __ldg(rp + 2 * lane);
            float4 p1 = __ldg(rp + 2 * lane + 1);
            float2* mp = reinterpret_cast<float2*>(&s->mind[k * GRPSZ + 2 * lane]);
            float2 mo = *mp;

            float dx = p0.x - cx, dy = p0.y - cy, dz = p0.z - cz;
            float d0 = dx * dx; d0 = fmaf(dy, dy, d0); d0 = fmaf(dz, dz, d0);
            dx = p1.x - cx; dy = p1.y - cy; dz = p1.z - cz;
            float d1 = dx * dx; d1 = fmaf(dy, dy, d1); d1 = fmaf(dz, dz, d1);

            float mm0 = fminf(mo.x, d0);
            float mm1 = fminf(mo.y, d1);
            *mp = make_float2(mm0, mm1);

            unsigned i0 = __float_as_uint(p0.w), i1 = __float_as_uint(p1.w);
            float bv = fmaxf(mm0, mm1);
            bool t0 = (mm0 == bv), t1 = (mm1 == bv);
            unsigned bi = t0 ? (t1 ? min(i0, i1) : i0) : i1;
            bool pick0 = t0 && (!t1 || i0 < i1);
            float bx = pick0 ? p0.x : p1.x;
            float by = pick0 ? p0.y : p1.y;
            float bz = pick0 ? p0.z : p1.z;

            unsigned vb = __float_as_uint(bv);                  // d>=0
            unsigned wv = __reduce_max_sync(0xffffffffu, vb);
            unsigned cd = (vb == wv) ? bi : 0xffffffffu;
            unsigned wi = __reduce_min_sync(0xffffffffu, cd);
            if (vb == wv && bi == wi) {                         // unique (idx unique)
                *reinterpret_cast<uint4*>(&s->meta[k]) =
                    make_uint4(wv, wi, __float_as_uint(bx), __float_as_uint(by));
                s->meta[k].z = bz;
            }
        }
        __syncthreads();

        // ---- block reduce: 256 metas -> 16 warp partials ----
        {
            unsigned v = 0, i = 0xffffffffu, xw = 0, yw = 0, zw = 0;
            if (lane < NGRP_C / NWARPS) {                       // 16 metas per warp
                int k = (int)warp * (NGRP_C / NWARPS) + (int)lane;
                uint4 w4 = *reinterpret_cast<const uint4*>(&s->meta[k]);
                v = w4.x; i = w4.y; xw = w4.z; yw = w4.w;
                zw = __float_as_uint(s->meta[k].z);
            }
            unsigned bv = __reduce_max_sync(0xffffffffu, v);
            unsigned bc = (v == bv) ? i : 0xffffffffu;
            unsigned bi = __reduce_min_sync(0xffffffffu, bc);
            if (v == bv && i == bi) {
                *reinterpret_cast<uint4*>(&s->warpred[warp]) =
                    make_uint4(bv, bi, xw, yw);
                s->warpred[warp].z = __uint_as_float(zw);
            }
        }
        __syncthreads();

        const int par = t & 1;

        // ---- warp0: reduce 16 warp partials, push to all 8 peers ----
        if (warp == 0) {
            unsigned v = 0, i = 0xffffffffu, xw = 0, yw = 0, zw = 0;
            if (lane < NWARPS) {
                uint4 w4 = *reinterpret_cast<const uint4*>(&s->warpred[lane]);
                v = w4.x; i = w4.y; xw = w4.z; yw = w4.w;
                zw = __float_as_uint(s->warpred[lane].z);
            }
            unsigned bv = __reduce_max_sync(0xffffffffu, v);
            unsigned bc = (v == bv) ? i : 0xffffffffu;
            unsigned bi = __reduce_min_sync(0xffffffffu, bc);
            unsigned msk = __ballot_sync(0xffffffffu, bc == bi);
            int L = __ffs(msk) - 1;
            xw = __shfl_sync(0xffffffffu, xw, L);
            yw = __shfl_sync(0xffffffffu, yw, L);
            zw = __shfl_sync(0xffffffffu, zw, L);
            if (lane < CSIZE) {
                unsigned ra = par ? rs1 : rs0;
                st_cluster_v4(ra, bv, bi, xw, yw);
                st_cluster_u32(ra + 16, zw);
            }
        }

        cluster_bar();   // one cluster barrier per step

        // ---- EVERY warp reduces the 8 slots -> next centroid in registers ----
        {
            unsigned v = 0, i = 0xffffffffu, xw = 0, yw = 0, zw = 0;
            if (lane < CSIZE) {
                uint4 w4 = *reinterpret_cast<const uint4*>(&s->slots[par][lane]);
                v = w4.x; i = w4.y; xw = w4.z; yw = w4.w;
                zw = __float_as_uint(s->slots[par][lane].z);
            }
            unsigned cv = __reduce_max_sync(0xffffffffu, v);
            unsigned cc = (v == cv) ? i : 0xffffffffu;
            unsigned ci = __reduce_min_sync(0xffffffffu, cc);
            unsigned msk = __ballot_sync(0xffffffffu, cc == ci);
            int W = __ffs(msk) - 1;
            cx = __uint_as_float(__shfl_sync(0xffffffffu, xw, W));
            cy = __uint_as_float(__shfl_sync(0xffffffffu, yw, W));
            cz = __uint_as_float(__shfl_sync(0xffffffffu, zw, W));
            if (rank == 0 && tid == 0) {
                float* o = out + ((size_t)batch * NSAMP + (size_t)t) * 3;
                o[0] = cx; o[1] = cy; o[2] = cz;
            }
        }
        // hazards: meta/mind/queue rewrites of step t+1 are fenced from step t
        // readers by the reset __syncthreads; slots are parity double-buffered
        // and ordered by the cluster barrier (same argument as prior rounds).
    }

    cluster_bar();  // keep CTAs alive until all DSMEM traffic has landed
}

extern "C" void kernel_launch(void* const* d_in, const int* in_sizes, int n_in,
                              void* d_out, int out_size) {
    (void)in_sizes; (void)n_in; (void)out_size;
    const float* xyz = (const float*)d_in[0];
    float* out = (float*)d_out;

    cudaFuncSetAttribute(fps_kernel,
                         cudaFuncAttributeMaxDynamicSharedMemorySize,
                         (int)sizeof(Smem));

    cudaLaunchConfig_t cfg = {};
    cfg.gridDim  = dim3(NB * CSIZE, 1, 1);   // 64 CTAs
    cfg.blockDim = dim3(TPB, 1, 1);
    cfg.dynamicSmemBytes = sizeof(Smem);
    cfg.stream = 0;

    cudaLaunchAttribute attr[1];
    attr[0].id = cudaLaunchAttributeClusterDimension;
    attr[0].val.clusterDim.x = CSIZE;
    attr[0].val.clusterDim.y = 1;
    attr[0].val.clusterDim.z = 1;
    cfg.attrs = attr;
    cfg.numAttrs = 1;

    cudaLaunchKernelEx(&cfg, fps_kernel, xyz, out);
}